// round 2
// baseline (speedup 1.0000x reference)
#include <cuda_runtime.h>
#include <math.h>

#define DEG2RAD 0.017453292519943295f
#define RAD2DEG 57.29577951308232f
#define TINY    1e-6f

__global__ __launch_bounds__(256)
void fk_kernel(const float* __restrict__ theta,
               const float* __restrict__ dh,
               float* __restrict__ out, int B) {
    __shared__ float s_a[6], s_d[6], s_ca[6], s_sa[6], s_off[6];
    int tx = threadIdx.x;
    if (tx < 6) {
        float al = dh[tx * 4 + 1] * DEG2RAD;
        s_ca[tx]  = cosf(al);
        s_sa[tx]  = sinf(al);
        s_a[tx]   = dh[tx * 4 + 0];
        s_d[tx]   = dh[tx * 4 + 2];
        s_off[tx] = dh[tx * 4 + 3];
    }
    __syncthreads();

    int i = blockIdx.x * blockDim.x + threadIdx.x;
    if (i >= B) return;

    // Vectorized load of the 6 joint angles (24B stride -> 8B aligned)
    const float2* thp = (const float2*)(theta + (size_t)i * 6);
    float2 v0 = thp[0], v1 = thp[1], v2 = thp[2];
    float th[6] = {v0.x, v0.y, v1.x, v1.y, v2.x, v2.y};

    // T held as 3x4 affine (implicit last row [0,0,0,1])
    float T[3][4];
    {
        float s, c;
        sincosf((th[0] + s_off[0]) * DEG2RAD, &s, &c);
        float ca = s_ca[0], sa = s_sa[0], a = s_a[0], d = s_d[0];
        T[0][0] = c;      T[0][1] = -c * 0.f - s; T[0][2] = 0.f; T[0][3] = a;
        T[0][1] = -s;
        T[1][0] = s * ca; T[1][1] = c * ca; T[1][2] = -sa;  T[1][3] = -sa * d;
        T[2][0] = s * sa; T[2][1] = c * sa; T[2][2] = ca;   T[2][3] = ca * d;
    }

    #pragma unroll
    for (int j = 1; j < 6; j++) {
        float s, c;
        sincosf((th[j] + s_off[j]) * DEG2RAD, &s, &c);
        float ca = s_ca[j], sa = s_sa[j], a = s_a[j], d = s_d[j];
        float sca = s * ca, ssa = s * sa;
        float cca = c * ca, csa = c * sa;
        float nsad = -sa * d, cad = ca * d;
        #pragma unroll
        for (int r = 0; r < 3; r++) {
            float t0 = T[r][0], t1 = T[r][1], t2 = T[r][2], t3 = T[r][3];
            T[r][0] = fmaf(t0, c,   fmaf(t1, sca, t2 * ssa));
            T[r][1] = fmaf(t0, -s,  fmaf(t1, cca, t2 * csa));
            T[r][2] = fmaf(t1, -sa, t2 * ca);
            T[r][3] = fmaf(t0, a,   fmaf(t1, nsad, fmaf(t2, cad, t3)));
        }
    }

    float T00 = T[0][0], T01 = T[0][1], T02 = T[0][2];
    float T10 = T[1][0], T11 = T[1][1], T12 = T[1][2];
    float T22 = T[2][2];

    bool cond = (fabsf(T12) <= TINY) && (fabsf(T22) <= TINY);

    float A1 = atan2f(T10, T11) * RAD2DEG;
    float B1 = atan2f(T02, T22) * RAD2DEG;
    float A2 = atan2f(-T01, T00) * RAD2DEG;

    // sin/cos of atan2(-T01, T00) computed algebraically (exact identity)
    float r2 = fmaf(T00, T00, T01 * T01);
    float h  = (r2 > 0.f) ? rsqrtf(r2) : 0.f;
    float sA = -T01 * h;
    float cA =  T00 * h;

    float B2 = atan2f(T02, fmaf(cA, T00, -sA * T01)) * RAD2DEG;
    float C2 = atan2f(-T12, T22) * RAD2DEG;

    float A  = cond ? A1 : A2;
    float Bd = cond ? B1 : B2;
    float C  = cond ? 0.f : C2;

    float2* op = (float2*)(out + (size_t)i * 6);
    op[0] = make_float2(T[0][3], T[1][3]);
    op[1] = make_float2(T[2][3], A);
    op[2] = make_float2(Bd, C);
}

extern "C" void kernel_launch(void* const* d_in, const int* in_sizes, int n_in,
                              void* d_out, int out_size) {
    const float* theta = (const float*)d_in[0];
    const float* dh    = (const float*)d_in[1];
    float* out         = (float*)d_out;
    int B = in_sizes[0] / 6;
    int block = 256;
    int grid = (B + block - 1) / block;
    fk_kernel<<<grid, block>>>(theta, dh, out, B);
}

// round 3
// speedup vs baseline: 1.0094x; 1.0094x over previous
#include <cuda_runtime.h>
#include <math.h>

#define DEG2RAD 0.017453292519943295f
#define RAD2DEG 57.29577951308232f
#define TINY    1e-6f

__global__ __launch_bounds__(256)
void fk_kernel(const float* __restrict__ theta,
               const float* __restrict__ dh,
               float* __restrict__ out, int B) {
    __shared__ float s_a[6], s_d[6], s_ca[6], s_sa[6], s_off[6];
    int tx = threadIdx.x;
    if (tx < 6) {
        float al = dh[tx * 4 + 1] * DEG2RAD;
        s_ca[tx]  = cosf(al);
        s_sa[tx]  = sinf(al);
        s_a[tx]   = dh[tx * 4 + 0];
        s_d[tx]   = dh[tx * 4 + 2];
        s_off[tx] = dh[tx * 4 + 3];
    }
    __syncthreads();

    int i = blockIdx.x * blockDim.x + threadIdx.x;
    if (i >= B) return;

    // Vectorized load of the 6 joint angles (24B stride -> 8B aligned)
    const float2* thp = (const float2*)(theta + (size_t)i * 6);
    float2 v0 = thp[0], v1 = thp[1], v2 = thp[2];
    float th[6] = {v0.x, v0.y, v1.x, v1.y, v2.x, v2.y};

    // T held as 3x4 affine (implicit last row [0,0,0,1])
    float T[3][4];
    {
        float s, c;
        sincosf((th[0] + s_off[0]) * DEG2RAD, &s, &c);
        float ca = s_ca[0], sa = s_sa[0], a = s_a[0], d = s_d[0];
        T[0][0] = c;      T[0][1] = -c * 0.f - s; T[0][2] = 0.f; T[0][3] = a;
        T[0][1] = -s;
        T[1][0] = s * ca; T[1][1] = c * ca; T[1][2] = -sa;  T[1][3] = -sa * d;
        T[2][0] = s * sa; T[2][1] = c * sa; T[2][2] = ca;   T[2][3] = ca * d;
    }

    #pragma unroll
    for (int j = 1; j < 6; j++) {
        float s, c;
        sincosf((th[j] + s_off[j]) * DEG2RAD, &s, &c);
        float ca = s_ca[j], sa = s_sa[j], a = s_a[j], d = s_d[j];
        float sca = s * ca, ssa = s * sa;
        float cca = c * ca, csa = c * sa;
        float nsad = -sa * d, cad = ca * d;
        #pragma unroll
        for (int r = 0; r < 3; r++) {
            float t0 = T[r][0], t1 = T[r][1], t2 = T[r][2], t3 = T[r][3];
            T[r][0] = fmaf(t0, c,   fmaf(t1, sca, t2 * ssa));
            T[r][1] = fmaf(t0, -s,  fmaf(t1, cca, t2 * csa));
            T[r][2] = fmaf(t1, -sa, t2 * ca);
            T[r][3] = fmaf(t0, a,   fmaf(t1, nsad, fmaf(t2, cad, t3)));
        }
    }

    float T00 = T[0][0], T01 = T[0][1], T02 = T[0][2];
    float T10 = T[1][0], T11 = T[1][1], T12 = T[1][2];
    float T22 = T[2][2];

    bool cond = (fabsf(T12) <= TINY) && (fabsf(T22) <= TINY);

    float A1 = atan2f(T10, T11) * RAD2DEG;
    float B1 = atan2f(T02, T22) * RAD2DEG;
    float A2 = atan2f(-T01, T00) * RAD2DEG;

    // sin/cos of atan2(-T01, T00) computed algebraically (exact identity)
    float r2 = fmaf(T00, T00, T01 * T01);
    float h  = (r2 > 0.f) ? rsqrtf(r2) : 0.f;
    float sA = -T01 * h;
    float cA =  T00 * h;

    float B2 = atan2f(T02, fmaf(cA, T00, -sA * T01)) * RAD2DEG;
    float C2 = atan2f(-T12, T22) * RAD2DEG;

    float A  = cond ? A1 : A2;
    float Bd = cond ? B1 : B2;
    float C  = cond ? 0.f : C2;

    float2* op = (float2*)(out + (size_t)i * 6);
    op[0] = make_float2(T[0][3], T[1][3]);
    op[1] = make_float2(T[2][3], A);
    op[2] = make_float2(Bd, C);
}

extern "C" void kernel_launch(void* const* d_in, const int* in_sizes, int n_in,
                              void* d_out, int out_size) {
    const float* theta = (const float*)d_in[0];
    const float* dh    = (const float*)d_in[1];
    float* out         = (float*)d_out;
    int B = in_sizes[0] / 6;
    int block = 256;
    int grid = (B + block - 1) / block;
    fk_kernel<<<grid, block>>>(theta, dh, out, B);
}